// round 8
// baseline (speedup 1.0000x reference)
#include <cuda_runtime.h>

#define BATCH   16
#define KPTS    2048
#define NPOINT  2048
#define NCHUNK  16                    // x-sorted chunks per batch
#define CLEN    128                   // points per chunk
#define SBINS   256                   // counting-sort bins

#define TPB_S   256
#define TPB_A   256                   // A': 1 i-point per thread
#define NI_CH   (KPTS / TPB_A)        // 8 i-chunks per batch

#define TPB_B1  1024
#define NWARP_B (TPB_B1 / 32)
#define ELEMS_B (KPTS / TPB_B1)
#define FLT_BIG 3.402823466e38f

typedef unsigned long long u64;

// x-sorted point data (SoA) + |p|^2, permutation sorted->orig, chunk x-bounds
__device__ float g_sx[BATCH * KPTS];
__device__ float g_sy[BATCH * KPTS];
__device__ float g_sz[BATCH * KPTS];
__device__ float g_sw[BATCH * KPTS];
__device__ int   g_perm[BATCH * KPTS];
__device__ float g_clo[BATCH * NCHUNK];
__device__ float g_chi[BATCH * NCHUNK];
__device__ float g_value[BATCH * KPTS];

// ---- packed f32x2 helpers --------------------------------------------------
__device__ __forceinline__ u64 f2pack(float lo, float hi) {
    u64 r; asm("mov.b64 %0, {%1, %2};" : "=l"(r) : "f"(lo), "f"(hi)); return r;
}
__device__ __forceinline__ u64 fma2(u64 a, u64 b, u64 c) {
    u64 d; asm("fma.rn.f32x2 %0, %1, %2, %3;" : "=l"(d) : "l"(a), "l"(b), "l"(c));
    return d;
}
__device__ __forceinline__ void f2unpack(u64 v, float& lo, float& hi) {
    asm("mov.b64 {%0, %1}, %2;" : "=f"(lo), "=f"(hi) : "l"(v));
}
__device__ __forceinline__ void s_top2(float c, float& m1, float& m2) {
    float t = fmaxf(m1, c); m1 = fminf(m1, c); m2 = fminf(m2, t);
}
__device__ __forceinline__ void s_top3(float c, float& m1, float& m2, float& m3) {
    float t1 = fmaxf(m1, c); m1 = fminf(m1, c);
    float t2 = fmaxf(m2, t1); m2 = fminf(m2, t1); m3 = fminf(m3, t2);
}

// ---------------------------------------------------------------------------
// Kernel S: per-batch counting sort by x (256 bins) + chunk x-bounds.
// Within-bin order is atomic-nondeterministic, which is benign: all later
// computed distances are exact per-pair and min/max is order-invariant.
// ---------------------------------------------------------------------------
__global__ __launch_bounds__(TPB_S)
void sor_sort_kernel(const float* __restrict__ x) {
    __shared__ int   hist[SBINS];
    __shared__ int   cursor[SBINS];
    __shared__ float s_red[16];
    __shared__ float s_lo, s_scale;
    __shared__ float s_sorted[KPTS];   // sorted x for chunk bounds

    const int b   = blockIdx.x;
    const int tid = threadIdx.x;
    const int lane = tid & 31;
    const int warp = tid >> 5;
    const float* __restrict__ xb = x + b * 3 * KPTS;

    float xv[8];
    float lmin = FLT_BIG, lmax = -FLT_BIG;
    #pragma unroll
    for (int u = 0; u < 8; ++u) {
        xv[u] = xb[tid + u * TPB_S];
        lmin = fminf(lmin, xv[u]);
        lmax = fmaxf(lmax, xv[u]);
    }
    #pragma unroll
    for (int o = 16; o; o >>= 1) {
        lmin = fminf(lmin, __shfl_xor_sync(0xffffffffu, lmin, o));
        lmax = fmaxf(lmax, __shfl_xor_sync(0xffffffffu, lmax, o));
    }
    if (lane == 0) { s_red[warp] = lmin; s_red[8 + warp] = lmax; }
    hist[tid] = 0;
    __syncthreads();
    if (tid == 0) {
        float mn = s_red[0], mx = s_red[8];
        #pragma unroll
        for (int w = 1; w < 8; ++w) {
            mn = fminf(mn, s_red[w]); mx = fmaxf(mx, s_red[8 + w]);
        }
        s_lo = mn;
        float wdt = mx - mn;
        s_scale = (wdt > 0.f) ? ((float)SBINS / wdt) * 0.999999f : 0.f;
    }
    __syncthreads();

    const float lo = s_lo, scale = s_scale;
    int bin[8];
    #pragma unroll
    for (int u = 0; u < 8; ++u) {
        int bb = (int)((xv[u] - lo) * scale);
        bin[u] = min(max(bb, 0), SBINS - 1);
        atomicAdd(&hist[bin[u]], 1);
    }
    __syncthreads();
    if (tid == 0) {
        int acc = 0;
        for (int i = 0; i < SBINS; ++i) { cursor[i] = acc; acc += hist[i]; }
    }
    __syncthreads();

    #pragma unroll
    for (int u = 0; u < 8; ++u) {
        int idx = tid + u * TPB_S;
        int pos = atomicAdd(&cursor[bin[u]], 1);
        float px = xv[u];
        float py = xb[KPTS + idx];
        float pz = xb[2 * KPTS + idx];
        float sq = __fadd_rn(__fadd_rn(__fmul_rn(px, px), __fmul_rn(py, py)),
                             __fmul_rn(pz, pz));
        g_sx[b * KPTS + pos] = px;
        g_sy[b * KPTS + pos] = py;
        g_sz[b * KPTS + pos] = pz;
        g_sw[b * KPTS + pos] = sq;
        g_perm[b * KPTS + pos] = idx;
        s_sorted[pos] = px;
    }
    __syncthreads();

    if (tid < NCHUNK) {
        float clo = FLT_BIG, chi = -FLT_BIG;
        for (int k = 0; k < CLEN; ++k) {
            float v = s_sorted[tid * CLEN + k];
            clo = fminf(clo, v); chi = fmaxf(chi, v);
        }
        g_clo[b * NCHUNK + tid] = clo;
        g_chi[b * NCHUNK + tid] = chi;
    }
}

// ---- packed chunk scans ----------------------------------------------------
__device__ __forceinline__ void scan3(
    const ulonglong2* __restrict__ X, const ulonglong2* __restrict__ Y,
    const ulonglong2* __restrict__ Z, const ulonglong2* __restrict__ W,
    u64 ax, u64 ay, u64 az, float* C)   // C[6]: two top-3 chains
{
    #pragma unroll 4
    for (int q = 0; q < CLEN / 4; ++q) {
        ulonglong2 vx = X[q], vy = Y[q], vz = Z[q], vw = W[q];
        u64 d01 = fma2(vz.x, az, fma2(vy.x, ay, fma2(vx.x, ax, vw.x)));
        u64 d23 = fma2(vz.y, az, fma2(vy.y, ay, fma2(vx.y, ax, vw.y)));
        float l0, h0, l1, h1;
        f2unpack(d01, l0, h0); f2unpack(d23, l1, h1);
        s_top3(l0, C[0], C[1], C[2]); s_top3(h0, C[3], C[4], C[5]);
        s_top3(l1, C[0], C[1], C[2]); s_top3(h1, C[3], C[4], C[5]);
    }
}
__device__ __forceinline__ void scan2(
    const ulonglong2* __restrict__ X, const ulonglong2* __restrict__ Y,
    const ulonglong2* __restrict__ Z, const ulonglong2* __restrict__ W,
    u64 ax, u64 ay, u64 az, float* E)   // E[4]: two top-2 chains
{
    #pragma unroll 4
    for (int q = 0; q < CLEN / 4; ++q) {
        ulonglong2 vx = X[q], vy = Y[q], vz = Z[q], vw = W[q];
        u64 d01 = fma2(vz.x, az, fma2(vy.x, ay, fma2(vx.x, ax, vw.x)));
        u64 d23 = fma2(vz.y, az, fma2(vy.y, ay, fma2(vx.y, ax, vw.y)));
        float l0, h0, l1, h1;
        f2unpack(d01, l0, h0); f2unpack(d23, l1, h1);
        s_top2(l0, E[0], E[1]); s_top2(h0, E[2], E[3]);
        s_top2(l1, E[0], E[1]); s_top2(h1, E[2], E[3]);
    }
}

// ---------------------------------------------------------------------------
// Kernel A': pruned exact 2-NN on x-sorted points.
// grid = (8 i-chunks, 16 batches) x 256 threads, 1 point per thread.
// Own 2 chunks: top-3 including self, drop min (= self). Expansion outward:
// chunk skipped only when (x-gap)^2 > (m2 + si) * (1+1e-5) + 1e-7, i.e. it
// provably cannot contain a top-2 candidate. Block-vote gates chunk loads.
// ---------------------------------------------------------------------------
__global__ __launch_bounds__(TPB_A)
void sor_knn_pruned_kernel() {
    __shared__ __align__(16) float spx[CLEN];
    __shared__ __align__(16) float spy[CLEN];
    __shared__ __align__(16) float spz[CLEN];
    __shared__ __align__(16) float spw[CLEN];

    const int b   = blockIdx.y;
    const int ci  = blockIdx.x;
    const int tid = threadIdx.x;
    const int g   = b * KPTS + ci * TPB_A + tid;

    const float xi = g_sx[g];
    const float yi = g_sy[g];
    const float zi = g_sz[g];
    const float si = g_sw[g];
    const u64 ax = f2pack(-2.0f * xi, -2.0f * xi);
    const u64 ay = f2pack(-2.0f * yi, -2.0f * yi);
    const u64 az = f2pack(-2.0f * zi, -2.0f * zi);

    const ulonglong2* X = reinterpret_cast<const ulonglong2*>(spx);
    const ulonglong2* Y = reinterpret_cast<const ulonglong2*>(spy);
    const ulonglong2* Z = reinterpret_cast<const ulonglong2*>(spz);
    const ulonglong2* W = reinterpret_cast<const ulonglong2*>(spw);

    const int c0 = 2 * ci;            // own chunks: c0, c0+1

    // ---- own 2 chunks: top-3 including self ----
    float C[6] = {FLT_BIG, FLT_BIG, FLT_BIG, FLT_BIG, FLT_BIG, FLT_BIG};
    #pragma unroll
    for (int cc = c0; cc <= c0 + 1; ++cc) {
        const int base = b * KPTS + cc * CLEN;
        if (tid < CLEN) { spx[tid] = g_sx[base + tid]; spy[tid] = g_sy[base + tid]; }
        else { int k = tid - CLEN; spz[k] = g_sz[base + k]; spw[k] = g_sw[base + k]; }
        __syncthreads();
        scan3(X, Y, Z, W, ax, ay, az, C);
        __syncthreads();
    }
    // merge chains, drop min (self), keep (mA, mB) = top-2 excluding self
    float t1 = C[0], t2 = C[1], t3 = C[2];
    s_top3(C[3], t1, t2, t3);
    s_top3(C[4], t1, t2, t3);
    s_top3(C[5], t1, t2, t3);
    float mA = t2, mB = t3;

    // ---- outward expansion with pruning ----
    int l = c0 - 1, r = c0 + 2;
    bool lact = (l >= 0), ract = (r < NCHUNK);
    while (lact || ract) {
        if (ract) {
            float gap = g_clo[b * NCHUNK + r] - xi;
            float lim = __fadd_rn(mB, si);
            lim = lim + lim * 1e-5f + 1e-7f;
            int need = (gap <= 0.f) || (gap * gap <= lim);
            if (!__syncthreads_or(need)) {
                ract = false;
            } else {
                const int base = b * KPTS + r * CLEN;
                if (tid < CLEN) { spx[tid] = g_sx[base + tid]; spy[tid] = g_sy[base + tid]; }
                else { int k = tid - CLEN; spz[k] = g_sz[base + k]; spw[k] = g_sw[base + k]; }
                __syncthreads();
                if (need) {
                    float E[4] = {mA, mB, FLT_BIG, FLT_BIG};
                    scan2(X, Y, Z, W, ax, ay, az, E);
                    mA = E[0]; mB = E[1];
                    s_top2(E[2], mA, mB);
                    s_top2(E[3], mA, mB);
                }
                __syncthreads();
                ++r; ract = (r < NCHUNK);
            }
        }
        if (lact) {
            float gap = xi - g_chi[b * NCHUNK + l];
            float lim = __fadd_rn(mB, si);
            lim = lim + lim * 1e-5f + 1e-7f;
            int need = (gap <= 0.f) || (gap * gap <= lim);
            if (!__syncthreads_or(need)) {
                lact = false;
            } else {
                const int base = b * KPTS + l * CLEN;
                if (tid < CLEN) { spx[tid] = g_sx[base + tid]; spy[tid] = g_sy[base + tid]; }
                else { int k = tid - CLEN; spz[k] = g_sz[base + k]; spw[k] = g_sw[base + k]; }
                __syncthreads();
                if (need) {
                    float E[4] = {mA, mB, FLT_BIG, FLT_BIG};
                    scan2(X, Y, Z, W, ax, ay, az, E);
                    mA = E[0]; mB = E[1];
                    s_top2(E[2], mA, mB);
                    s_top2(E[3], mA, mB);
                }
                __syncthreads();
                --l; lact = (l >= 0);
            }
        }
    }

    const float value = (__fadd_rn(mA, si) + __fadd_rn(mB, si)) * 0.5f;
    g_value[b * KPTS + g_perm[g]] = value;
}

// ---------------------------------------------------------------------------
// Kernel B1: per-batch stats + stable compaction + tiled gather (unchanged).
// ---------------------------------------------------------------------------
__global__ __launch_bounds__(TPB_B1)
void sor_compact_gather_kernel(const float* __restrict__ x,
                               float* __restrict__ out) {
    __shared__ float sx[KPTS];
    __shared__ float sy[KPTS];
    __shared__ float sz[KPTS];
    __shared__ float sval[KPTS];
    __shared__ int   skept[KPTS];
    __shared__ float red[NWARP_B];
    __shared__ int   wofs[NWARP_B];
    __shared__ float s_mean, s_thr;
    __shared__ int   s_n;

    const int b    = blockIdx.x;
    const int tid  = threadIdx.x;
    const int lane = tid & 31;
    const int warp = tid >> 5;
    const float* __restrict__ xb = x + b * 3 * KPTS;
    float* __restrict__ ob = out + b * 3 * KPTS;

    #pragma unroll
    for (int t = tid; t < KPTS; t += TPB_B1) {
        sx[t]   = xb[t];
        sy[t]   = xb[KPTS + t];
        sz[t]   = xb[2 * KPTS + t];
        sval[t] = g_value[b * KPTS + t];
    }
    __syncthreads();

    // ---- mean ----
    float s = 0.0f;
    #pragma unroll
    for (int t = tid; t < KPTS; t += TPB_B1) s += sval[t];
    #pragma unroll
    for (int o = 16; o; o >>= 1) s += __shfl_xor_sync(0xffffffffu, s, o);
    if (lane == 0) red[warp] = s;
    __syncthreads();
    if (warp == 0) {
        float v = red[lane];
        #pragma unroll
        for (int o = 16; o; o >>= 1) v += __shfl_xor_sync(0xffffffffu, v, o);
        if (lane == 0) s_mean = v * (1.0f / (float)KPTS);
    }
    __syncthreads();
    const float mean = s_mean;

    // ---- std (ddof = 1) ----
    float s2 = 0.0f;
    #pragma unroll
    for (int t = tid; t < KPTS; t += TPB_B1) {
        float d = sval[t] - mean;
        s2 = __fmaf_rn(d, d, s2);
    }
    #pragma unroll
    for (int o = 16; o; o >>= 1) s2 += __shfl_xor_sync(0xffffffffu, s2, o);
    if (lane == 0) red[warp] = s2;
    __syncthreads();
    if (warp == 0) {
        float v = red[lane];
        #pragma unroll
        for (int o = 16; o; o >>= 1) v += __shfl_xor_sync(0xffffffffu, v, o);
        if (lane == 0) {
            float var = v / (float)(KPTS - 1);
            s_thr = __fadd_rn(s_mean, __fmul_rn(1.1f, sqrtf(var)));
        }
    }
    __syncthreads();
    const float thr = s_thr;

    // ---- stable compaction ----
    const int base_t = tid * ELEMS_B;
    unsigned mbits = 0;
    int c = 0;
    #pragma unroll
    for (int u = 0; u < ELEMS_B; ++u) {
        bool m = sval[base_t + u] <= thr;
        mbits |= (unsigned)m << u;
        c += (int)m;
    }
    int v = c;
    #pragma unroll
    for (int o = 1; o < 32; o <<= 1) {
        int t2 = __shfl_up_sync(0xffffffffu, v, o);
        if (lane >= o) v += t2;
    }
    if (lane == 31) wofs[warp] = v;
    __syncthreads();
    if (warp == 0) {
        int wv = wofs[lane];
        int inc = wv;
        #pragma unroll
        for (int o = 1; o < 32; o <<= 1) {
            int t3 = __shfl_up_sync(0xffffffffu, inc, o);
            if (lane >= o) inc += t3;
        }
        wofs[lane] = inc - wv;
        if (lane == 31) s_n = inc;
    }
    __syncthreads();
    int pos = (v - c) + wofs[warp];
    #pragma unroll
    for (int u = 0; u < ELEMS_B; ++u) {
        if ((mbits >> u) & 1u) skept[pos++] = base_t + u;
    }
    __syncthreads();

    // ---- tiled gather ----
    const int n = s_n;
    #pragma unroll
    for (int j = tid; j < NPOINT; j += TPB_B1) {
        int p = (j < n) ? j : (j % n);
        int idx = skept[p];
        ob[j]            = sx[idx];
        ob[KPTS + j]     = sy[idx];
        ob[2 * KPTS + j] = sz[idx];
    }
}

extern "C" void kernel_launch(void* const* d_in, const int* in_sizes, int n_in,
                              void* d_out, int out_size) {
    (void)in_sizes; (void)n_in; (void)out_size;
    const float* x = (const float*)d_in[0];
    float* out = (float*)d_out;

    sor_sort_kernel<<<BATCH, TPB_S>>>(x);
    sor_knn_pruned_kernel<<<dim3(NI_CH, BATCH), TPB_A>>>();
    sor_compact_gather_kernel<<<BATCH, TPB_B1>>>(x, out);
}

// round 9
// speedup vs baseline: 1.6391x; 1.6391x over previous
#include <cuda_runtime.h>

#define BATCH   16
#define KPTS    2048
#define NPOINT  2048

#define TPB_A   128
#define ICHUNK  (TPB_A * 2)           // 256 i-points per CTA (2 per thread)
#define NI_CH   (KPTS / ICHUNK)       // 8
#define JS      16                    // j-splits
#define JCH     (KPTS / JS)           // 128 j-points per chunk (== TPB_A)

#define TPB_B1  1024
#define NWARP_B (TPB_B1 / 32)         // 32
#define ELEMS_B (KPTS / TPB_B1)       // 2
#define FLT_BIG 3.402823466e38f

typedef unsigned long long u64;

// per-(batch, chunk, i) top-3 candidates (true squared distances, +sq_i),
// FLT_BIG padding where a chunk only contributes 2.
__device__ float4 g_part[BATCH * JS * KPTS];
__device__ float  g_value[BATCH * KPTS];

// ---- packed f32x2 helpers (sm_100a: fma.rn.f32x2 exists; min/max do NOT) ---
__device__ __forceinline__ u64 f2pack(float lo, float hi) {
    u64 r; asm("mov.b64 %0, {%1, %2};" : "=l"(r) : "f"(lo), "f"(hi)); return r;
}
__device__ __forceinline__ u64 fma2(u64 a, u64 b, u64 c) {
    u64 d; asm("fma.rn.f32x2 %0, %1, %2, %3;" : "=l"(d) : "l"(a), "l"(b), "l"(c));
    return d;
}
__device__ __forceinline__ void f2unpack(u64 v, float& lo, float& hi) {
    asm("mov.b64 {%0, %1}, %2;" : "=f"(lo), "=f"(hi) : "l"(v));
}

__device__ __forceinline__ void s_top2(float c, float& m1, float& m2) {
    float t = fmaxf(m1, c); m1 = fminf(m1, c); m2 = fminf(m2, t);
}
__device__ __forceinline__ void s_top3(float c, float& m1, float& m2, float& m3) {
    float t1 = fmaxf(m1, c); m1 = fminf(m1, c);
    float t2 = fmaxf(m2, t1); m2 = fminf(m2, t1); m3 = fminf(m3, t2);
}

// ---- packed chunk scan ------------------------------------------------------
// Two accumulators (i0, i1); distances for 2 j's at a time via fma.rn.f32x2;
// two scalar top-k chains per accumulator (lo-lane j's and hi-lane j's).
// TA/TB = 3 for the accumulator whose self lies in this chunk, else 2.
template<int TA, int TB>
__device__ __forceinline__ void scan_chunk(
    const ulonglong2* __restrict__ px2, const ulonglong2* __restrict__ py2,
    const ulonglong2* __restrict__ pz2, const ulonglong2* __restrict__ pw2,
    u64 ax0, u64 ay0, u64 az0, u64 ax1, u64 ay1, u64 az1,
    float* A, float* B)   // A[0..2*TA), B[0..2*TB): {even chain, odd chain}
{
    #pragma unroll 8
    for (int q = 0; q < JCH / 4; ++q) {
        ulonglong2 X = px2[q], Y = py2[q], Z = pz2[q], W = pw2[q];

        u64 d01 = fma2(Z.x, az0, fma2(Y.x, ay0, fma2(X.x, ax0, W.x)));
        u64 d23 = fma2(Z.y, az0, fma2(Y.y, ay0, fma2(X.y, ax0, W.y)));
        float l0, h0, l1, h1;
        f2unpack(d01, l0, h0); f2unpack(d23, l1, h1);
        if (TA == 3) {
            s_top3(l0, A[0], A[1], A[2]); s_top3(h0, A[3], A[4], A[5]);
            s_top3(l1, A[0], A[1], A[2]); s_top3(h1, A[3], A[4], A[5]);
        } else {
            s_top2(l0, A[0], A[1]); s_top2(h0, A[2], A[3]);
            s_top2(l1, A[0], A[1]); s_top2(h1, A[2], A[3]);
        }

        u64 e01 = fma2(Z.x, az1, fma2(Y.x, ay1, fma2(X.x, ax1, W.x)));
        u64 e23 = fma2(Z.y, az1, fma2(Y.y, ay1, fma2(X.y, ax1, W.y)));
        f2unpack(e01, l0, h0); f2unpack(e23, l1, h1);
        if (TB == 3) {
            s_top3(l0, B[0], B[1], B[2]); s_top3(h0, B[3], B[4], B[5]);
            s_top3(l1, B[0], B[1], B[2]); s_top3(h1, B[3], B[4], B[5]);
        } else {
            s_top2(l0, B[0], B[1]); s_top2(h0, B[2], B[3]);
            s_top2(l1, B[0], B[1]); s_top2(h1, B[2], B[3]);
        }
    }
}

// merge the two chains (exact min/max union), add si to survivors
__device__ __forceinline__ float4 fin2(const float* C, float si) {
    float M1 = C[0], M2 = C[1];
    s_top2(C[2], M1, M2);
    s_top2(C[3], M1, M2);
    return make_float4(__fadd_rn(M1, si), __fadd_rn(M2, si), FLT_BIG, FLT_BIG);
}
__device__ __forceinline__ float4 fin3(const float* C, float si) {
    float M1 = C[0], M2 = C[1], M3 = C[2];
    s_top3(C[3], M1, M2, M3);
    s_top3(C[4], M1, M2, M3);
    s_top3(C[5], M1, M2, M3);
    return make_float4(__fadd_rn(M1, si), __fadd_rn(M2, si), __fadd_rn(M3, si),
                       FLT_BIG);
}

// ---------------------------------------------------------------------------
// Kernel A: packed partial kNN. grid = (8, 16, 16) = 2048 CTAs x 128 threads.
// __launch_bounds__(128, 12): cap regs at ~42 -> 12 CTAs/SM = 48 warps/SM.
// Self is INCLUDED (top-3 on the one accumulator whose self is in this chunk);
// the global merge drops the minimum == reference top_k(k+1)/drop-smallest.
// ---------------------------------------------------------------------------
__global__ __launch_bounds__(TPB_A, 12)
void sor_knn_partial_kernel(const float* __restrict__ x) {
    __shared__ __align__(16) float spx[JCH];
    __shared__ __align__(16) float spy[JCH];
    __shared__ __align__(16) float spz[JCH];
    __shared__ __align__(16) float spw[JCH];

    const int b   = blockIdx.z;
    const int ci  = blockIdx.x;
    const int cj  = blockIdx.y;
    const int tid = threadIdx.x;
    const float* __restrict__ xb = x + b * 3 * KPTS;

    {   // stage j-chunk in SoA form (JCH == TPB_A)
        int g = cj * JCH + tid;
        float px = xb[g];
        float py = xb[KPTS + g];
        float pz = xb[2 * KPTS + g];
        float sq = __fadd_rn(__fadd_rn(__fmul_rn(px, px), __fmul_rn(py, py)),
                             __fmul_rn(pz, pz));
        spx[tid] = px; spy[tid] = py; spz[tid] = pz; spw[tid] = sq;
    }
    __syncthreads();

    const int i0 = ci * ICHUNK + tid;
    const int i1 = i0 + TPB_A;

    float x0 = xb[i0], y0 = xb[KPTS + i0], z0 = xb[2 * KPTS + i0];
    float x1 = xb[i1], y1 = xb[KPTS + i1], z1 = xb[2 * KPTS + i1];
    const u64 ax0 = f2pack(-2.0f * x0, -2.0f * x0);
    const u64 ay0 = f2pack(-2.0f * y0, -2.0f * y0);
    const u64 az0 = f2pack(-2.0f * z0, -2.0f * z0);
    const u64 ax1 = f2pack(-2.0f * x1, -2.0f * x1);
    const u64 ay1 = f2pack(-2.0f * y1, -2.0f * y1);
    const u64 az1 = f2pack(-2.0f * z1, -2.0f * z1);
    const float si0 = __fadd_rn(__fadd_rn(__fmul_rn(x0, x0), __fmul_rn(y0, y0)),
                                __fmul_rn(z0, z0));
    const float si1 = __fadd_rn(__fadd_rn(__fmul_rn(x1, x1), __fmul_rn(y1, y1)),
                                __fmul_rn(z1, z1));

    const ulonglong2* px2 = reinterpret_cast<const ulonglong2*>(spx);
    const ulonglong2* py2 = reinterpret_cast<const ulonglong2*>(spy);
    const ulonglong2* pz2 = reinterpret_cast<const ulonglong2*>(spz);
    const ulonglong2* pw2 = reinterpret_cast<const ulonglong2*>(spw);

    // i0 lives in chunk 2*ci, i1 in chunk 2*ci+1
    const int selfacc = (cj == 2 * ci) ? 0 : ((cj == 2 * ci + 1) ? 1 : -1);

    float A[6] = {FLT_BIG, FLT_BIG, FLT_BIG, FLT_BIG, FLT_BIG, FLT_BIG};
    float B[6] = {FLT_BIG, FLT_BIG, FLT_BIG, FLT_BIG, FLT_BIG, FLT_BIG};

    float4 r0, r1;
    if (selfacc == 0) {
        scan_chunk<3, 2>(px2, py2, pz2, pw2, ax0, ay0, az0, ax1, ay1, az1, A, B);
        r0 = fin3(A, si0);
        r1 = fin2(B, si1);
    } else if (selfacc == 1) {
        scan_chunk<2, 3>(px2, py2, pz2, pw2, ax0, ay0, az0, ax1, ay1, az1, A, B);
        r0 = fin2(A, si0);
        r1 = fin3(B, si1);
    } else {
        scan_chunk<2, 2>(px2, py2, pz2, pw2, ax0, ay0, az0, ax1, ay1, az1, A, B);
        r0 = fin2(A, si0);
        r1 = fin2(B, si1);
    }

    float4* __restrict__ gp = g_part + (b * JS + cj) * KPTS;
    gp[i0] = r0;
    gp[i1] = r1;
}

// ---------------------------------------------------------------------------
// Kernel B0: global top-3 across chunks, drop min (self), value = (m2+m3)/2.
// grid = 128 CTAs x 256 threads.
// ---------------------------------------------------------------------------
__global__ __launch_bounds__(256)
void sor_merge_kernel() {
    const int g = blockIdx.x * 256 + threadIdx.x;   // [0, BATCH*KPTS)
    const int b = g >> 11;
    const int i = g & (KPTS - 1);

    float m1 = FLT_BIG, m2 = FLT_BIG, m3 = FLT_BIG;
    #pragma unroll
    for (int c = 0; c < JS; ++c) {
        float4 pr = g_part[(b * JS + c) * KPTS + i];
        s_top3(pr.x, m1, m2, m3);
        s_top3(pr.y, m1, m2, m3);
        s_top3(pr.z, m1, m2, m3);
    }
    // m1 == self (~0), dropped; mean of the two true nearest
    g_value[g] = __fadd_rn(m2, m3) * 0.5f;
}

// ---------------------------------------------------------------------------
// Kernel B1: per-batch stats + stable compaction + tiled gather.
// grid = 16, 1024 threads.
// ---------------------------------------------------------------------------
__global__ __launch_bounds__(TPB_B1)
void sor_compact_gather_kernel(const float* __restrict__ x,
                               float* __restrict__ out) {
    __shared__ float sx[KPTS];
    __shared__ float sy[KPTS];
    __shared__ float sz[KPTS];
    __shared__ float sval[KPTS];
    __shared__ int   skept[KPTS];
    __shared__ float red[NWARP_B];
    __shared__ int   wofs[NWARP_B];
    __shared__ float s_mean, s_thr;
    __shared__ int   s_n;

    const int b    = blockIdx.x;
    const int tid  = threadIdx.x;
    const int lane = tid & 31;
    const int warp = tid >> 5;
    const float* __restrict__ xb = x + b * 3 * KPTS;
    float* __restrict__ ob = out + b * 3 * KPTS;

    #pragma unroll
    for (int t = tid; t < KPTS; t += TPB_B1) {
        sx[t]   = xb[t];
        sy[t]   = xb[KPTS + t];
        sz[t]   = xb[2 * KPTS + t];
        sval[t] = g_value[b * KPTS + t];
    }
    __syncthreads();

    // ---- mean ----
    float s = 0.0f;
    #pragma unroll
    for (int t = tid; t < KPTS; t += TPB_B1) s += sval[t];
    #pragma unroll
    for (int o = 16; o; o >>= 1) s += __shfl_xor_sync(0xffffffffu, s, o);
    if (lane == 0) red[warp] = s;
    __syncthreads();
    if (warp == 0) {
        float v = red[lane];
        #pragma unroll
        for (int o = 16; o; o >>= 1) v += __shfl_xor_sync(0xffffffffu, v, o);
        if (lane == 0) s_mean = v * (1.0f / (float)KPTS);
    }
    __syncthreads();
    const float mean = s_mean;

    // ---- std (ddof = 1) ----
    float s2 = 0.0f;
    #pragma unroll
    for (int t = tid; t < KPTS; t += TPB_B1) {
        float d = sval[t] - mean;
        s2 = __fmaf_rn(d, d, s2);
    }
    #pragma unroll
    for (int o = 16; o; o >>= 1) s2 += __shfl_xor_sync(0xffffffffu, s2, o);
    if (lane == 0) red[warp] = s2;
    __syncthreads();
    if (warp == 0) {
        float v = red[lane];
        #pragma unroll
        for (int o = 16; o; o >>= 1) v += __shfl_xor_sync(0xffffffffu, v, o);
        if (lane == 0) {
            float var = v / (float)(KPTS - 1);
            s_thr = __fadd_rn(s_mean, __fmul_rn(1.1f, sqrtf(var)));
        }
    }
    __syncthreads();
    const float thr = s_thr;

    // ---- stable compaction ----
    const int base_t = tid * ELEMS_B;
    unsigned mbits = 0;
    int c = 0;
    #pragma unroll
    for (int u = 0; u < ELEMS_B; ++u) {
        bool m = sval[base_t + u] <= thr;
        mbits |= (unsigned)m << u;
        c += (int)m;
    }
    int v = c;
    #pragma unroll
    for (int o = 1; o < 32; o <<= 1) {
        int t2 = __shfl_up_sync(0xffffffffu, v, o);
        if (lane >= o) v += t2;
    }
    if (lane == 31) wofs[warp] = v;
    __syncthreads();
    if (warp == 0) {
        int wv = wofs[lane];
        int inc = wv;
        #pragma unroll
        for (int o = 1; o < 32; o <<= 1) {
            int t3 = __shfl_up_sync(0xffffffffu, inc, o);
            if (lane >= o) inc += t3;
        }
        wofs[lane] = inc - wv;
        if (lane == 31) s_n = inc;
    }
    __syncthreads();
    int pos = (v - c) + wofs[warp];
    #pragma unroll
    for (int u = 0; u < ELEMS_B; ++u) {
        if ((mbits >> u) & 1u) skept[pos++] = base_t + u;
    }
    __syncthreads();

    // ---- tiled gather ----
    const int n = s_n;
    #pragma unroll
    for (int j = tid; j < NPOINT; j += TPB_B1) {
        int p = (j < n) ? j : (j % n);
        int idx = skept[p];
        ob[j]            = sx[idx];
        ob[KPTS + j]     = sy[idx];
        ob[2 * KPTS + j] = sz[idx];
    }
}

extern "C" void kernel_launch(void* const* d_in, const int* in_sizes, int n_in,
                              void* d_out, int out_size) {
    (void)in_sizes; (void)n_in; (void)out_size;
    const float* x = (const float*)d_in[0];
    float* out = (float*)d_out;

    sor_knn_partial_kernel<<<dim3(NI_CH, JS, BATCH), TPB_A>>>(x);
    sor_merge_kernel<<<(BATCH * KPTS) / 256, 256>>>();
    sor_compact_gather_kernel<<<BATCH, TPB_B1>>>(x, out);
}